// round 13
// baseline (speedup 1.0000x reference)
#include <cuda_runtime.h>
#include <cuda_fp16.h>
#include <math.h>
#include <stdint.h>

#define B_SZ 512
#define D_SZ 512
#define C_SZ 100000
#define BN 128
#define BM 128
#define BK 64
#define NK 8                       // 512/64
#define NSTAGE 3
#define NTILES_N 782               // ceil(100000/128)
#define PITCH 72                   // halves per smem row (144 B) — conflict-free ldsm
#define STAGE_B (2 * 128 * PITCH * 2)      // A half + B half = 36864 B
#define B_PART  (128 * PITCH * 2)          // 18432
#define WINV_OFF (NSTAGE * STAGE_B)        // 110592
#define SMEM_BYTES (WINV_OFF + BN * 4)     // 111104
#define S_SCALE 30.0f
#define LMAX 31.0f
#define COS_M 0.8775825618903728f
#define SIN_M 0.47942553860420300f

// ---------------- static device scratch -------------------------------------
__device__ __half g_xh[B_SZ * D_SZ];            // normalized fp16 x
__device__ float g_xn[B_SZ * D_SZ];             // normalized fp32 x (finalize)
__device__ float g_rowsum[B_SZ];

// ---------------- PTX helpers ------------------------------------------------
__device__ __forceinline__ uint32_t smem_u32(const void* p) {
    uint32_t a;
    asm("{ .reg .u64 t; cvta.to.shared.u64 t, %1; cvt.u32.u64 %0, t; }" : "=r"(a) : "l"(p));
    return a;
}
__device__ __forceinline__ void cp16(uint32_t dst, const void* src) {
    asm volatile("cp.async.cg.shared.global [%0], [%1], 16;" :: "r"(dst), "l"(src));
}
#define CP_COMMIT() asm volatile("cp.async.commit_group;" ::: "memory")
#define CP_WAIT(n)  asm volatile("cp.async.wait_group %0;" :: "n"(n) : "memory")

__device__ __forceinline__ void ldsm4(uint32_t* r, uint32_t addr) {
    asm volatile("ldmatrix.sync.aligned.m8n8.x4.shared.b16 {%0,%1,%2,%3}, [%4];"
        : "=r"(r[0]), "=r"(r[1]), "=r"(r[2]), "=r"(r[3]) : "r"(addr));
}
// fp16 inputs, fp16 accumulators
__device__ __forceinline__ void mma16816h(uint32_t* d, const uint32_t* a, uint32_t b0, uint32_t b1) {
    asm volatile(
        "mma.sync.aligned.m16n8k16.row.col.f16.f16.f16.f16 "
        "{%0,%1}, {%2,%3,%4,%5}, {%6,%7}, {%0,%1};"
        : "+r"(d[0]), "+r"(d[1])
        : "r"(a[0]), "r"(a[1]), "r"(a[2]), "r"(a[3]), "r"(b0), "r"(b1));
}

// ---------------------------------------------------------------------------
// Kernel 1: normalize x rows -> g_xn (fp32) + g_xh (fp16); zero g_rowsum/out
// ---------------------------------------------------------------------------
__global__ void xnorm_kernel(const float* __restrict__ x, float* __restrict__ out) {
    const int row = blockIdx.x;
    const int tid = threadIdx.x;   // 128
    const float* xr = x + (size_t)row * D_SZ;

    float ss = 0.f;
    float v[4];
    #pragma unroll
    for (int i = 0; i < 4; i++) { v[i] = xr[tid + i * 128]; ss += v[i] * v[i]; }
    __shared__ float red[128];
    red[tid] = ss;
    __syncthreads();
    #pragma unroll
    for (int off = 64; off > 0; off >>= 1) {
        if (tid < off) red[tid] += red[tid + off];
        __syncthreads();
    }
    const float inv = 1.f / fmaxf(sqrtf(red[0]), 1e-12f);
    #pragma unroll
    for (int i = 0; i < 4; i++) {
        int d = tid + i * 128;
        float nv = v[i] * inv;
        g_xn[(size_t)row * D_SZ + d] = nv;
        g_xh[(size_t)row * D_SZ + d] = __float2half_rn(nv);
    }
    if (tid == 0) {
        g_rowsum[row] = 0.f;
        if (row == 0) out[0] = 0.f;
    }
}

// ---------------------------------------------------------------------------
// Kernel 2: fused GEMM — streams RAW fp32 weights, converts to fp16 in-flight,
// computes per-class inv-norms on the way, HMMA fp16, streaming exp-sum
// epilogue. Pipeline per k-step: STS(k+1) | LDG(k+2)+cpA(k+2) | compute(k).
// Grid (m=4, n=782) so 4 CTAs share each B tile via L2.
// ---------------------------------------------------------------------------
__global__ void __launch_bounds__(256, 1) gemm_fused_kernel(const float* __restrict__ w) {
    extern __shared__ __align__(16) char smem[];
    const int tid = threadIdx.x;
    const int warp = tid >> 5;
    const int lane = tid & 31;
    const int wm = warp & 1;
    const int wn = warp >> 1;
    const int m0 = blockIdx.x * BM;
    const int n0 = blockIdx.y * BN;
    const uint32_t sb = smem_u32(smem);
    float* swinv = reinterpret_cast<float*>(smem + WINV_OFF);

    const __half* srcA = g_xh + (size_t)m0 * D_SZ;

    // B-LDG mapping: warp owns rows [warp*16, warp*16+16); per i (0..7) the
    // two half-warps cover rows warp*16 + i*2 + (lane>>4); lane&15 covers the
    // row's 64 floats in 16B pieces (perfectly coalesced 256B bursts).
    const int lrow_ofs = warp * 16 + (lane >> 4);
    const int lpiece = lane & 15;

    uint32_t acc[4][4][2];
    #pragma unroll
    for (int a = 0; a < 4; a++)
        #pragma unroll
        for (int b = 0; b < 4; b++) { acc[a][b][0] = 0u; acc[a][b][1] = 0u; }

    float4 breg[8];
    float ssq[8];
    #pragma unroll
    for (int i = 0; i < 8; i++) ssq[i] = 0.f;

    auto ldgB = [&](int k0) {
        #pragma unroll
        for (int i = 0; i < 8; i++) {
            int grow = n0 + lrow_ofs + i * 2;
            if (grow < C_SZ)
                breg[i] = *reinterpret_cast<const float4*>(w + (size_t)grow * D_SZ + k0 + lpiece * 4);
            else
                breg[i] = make_float4(0.f, 0.f, 0.f, 0.f);
        }
    };
    auto stsB = [&](int stage) {
        const uint32_t dstb = sb + (uint32_t)stage * STAGE_B + B_PART;
        #pragma unroll
        for (int i = 0; i < 8; i++) {
            float4 v = breg[i];
            ssq[i] += v.x * v.x + v.y * v.y + v.z * v.z + v.w * v.w;
            __half2 h0 = __floats2half2_rn(v.x, v.y);
            __half2 h1 = __floats2half2_rn(v.z, v.w);
            uint2 o;
            o.x = *reinterpret_cast<uint32_t*>(&h0);
            o.y = *reinterpret_cast<uint32_t*>(&h1);
            *reinterpret_cast<uint2*>(smem + (dstb - sb) + (lrow_ofs + i * 2) * (PITCH * 2) + lpiece * 8) = o;
        }
    };
    auto load_A = [&](int stage, int k0) {
        const uint32_t dst = sb + (uint32_t)stage * STAGE_B;
        #pragma unroll
        for (int j = 0; j < 4; j++) {
            int idx = tid + 256 * j;            // 0..1023
            int row = idx >> 3;
            int piece = idx & 7;
            cp16(dst + (uint32_t)(row * (PITCH * 2) + piece * 16),
                 srcA + (size_t)row * D_SZ + k0 + piece * 8);
        }
    };

    // ---- prologue ----
    ldgB(0);
    load_A(0, 0); CP_COMMIT();
    load_A(1, BK); CP_COMMIT();
    stsB(0);                       // waits on LDG(0) data
    ldgB(BK);
    CP_WAIT(1);
    __syncthreads();               // A0 + fp16 B0 visible

    const int lrow = lane & 15;
    const int lcol = (lane >> 4) * 8;

    for (int k = 0; k < NK; k++) {
        if (k + 1 < NK) stsB((k + 1) % NSTAGE);
        if (k + 2 < NK) {
            ldgB((k + 2) * BK);
            load_A((k + 2) % NSTAGE, (k + 2) * BK);
            CP_COMMIT();
        }

        const uint32_t aoff = sb + (uint32_t)(k % NSTAGE) * STAGE_B;
        const uint32_t boff = aoff + B_PART;
        #pragma unroll
        for (int kk = 0; kk < BK; kk += 16) {
            uint32_t af[4][4], bf[2][4];
            #pragma unroll
            for (int mt = 0; mt < 4; mt++)
                ldsm4(af[mt], aoff + (uint32_t)((wm * 64 + mt * 16 + lrow) * PITCH + kk + lcol) * 2);
            #pragma unroll
            for (int nt2 = 0; nt2 < 2; nt2++)
                ldsm4(bf[nt2], boff + (uint32_t)((wn * 32 + nt2 * 16 + lrow) * PITCH + kk + lcol) * 2);
            #pragma unroll
            for (int mt = 0; mt < 4; mt++) {
                #pragma unroll
                for (int nt = 0; nt < 4; nt++) {
                    const uint32_t* bb = bf[nt >> 1];
                    uint32_t b0 = (nt & 1) ? bb[1] : bb[0];
                    uint32_t b1 = (nt & 1) ? bb[3] : bb[2];
                    mma16816h(acc[mt][nt], af[mt], b0, b1);
                }
            }
        }

        if (k + 1 < NK) { if (k + 2 < NK) { CP_WAIT(1); } else { CP_WAIT(0); } }
        __syncthreads();
    }

    // ---- per-class inv-norms (exact fp32, full K seen by this CTA) ---------
    #pragma unroll
    for (int i = 0; i < 8; i++) {
        float s = ssq[i];
        s += __shfl_xor_sync(0xffffffffu, s, 1);
        s += __shfl_xor_sync(0xffffffffu, s, 2);
        s += __shfl_xor_sync(0xffffffffu, s, 4);
        s += __shfl_xor_sync(0xffffffffu, s, 8);
        if ((lane & 15) == 0)
            swinv[lrow_ofs + i * 2] = (s > 0.f) ? rsqrtf(s) * S_SCALE : 0.f;
    }
    __syncthreads();

    // ---- epilogue: logit = acc * winv*30; exp-sum per row -> atomic --------
    // pad classes have winv=0 -> logit 0 -> exp(-31) (negligible).
    const int rbase = m0 + wm * 64 + (lane >> 2);
    const int cl = wn * 32 + 2 * (lane & 3);

    #pragma unroll
    for (int mt = 0; mt < 4; mt++) {
        float es0 = 0.f, es1 = 0.f;
        #pragma unroll
        for (int nt = 0; nt < 4; nt++) {
            const int c0 = cl + nt * 8;
            const float s0 = swinv[c0], s1 = swinv[c0 + 1];
            float2 f01 = __half22float2(*reinterpret_cast<__half2*>(&acc[mt][nt][0]));
            float2 f23 = __half22float2(*reinterpret_cast<__half2*>(&acc[mt][nt][1]));
            es0 += __expf(fmaf(f01.x, s0, -LMAX));
            es0 += __expf(fmaf(f01.y, s1, -LMAX));
            es1 += __expf(fmaf(f23.x, s0, -LMAX));
            es1 += __expf(fmaf(f23.y, s1, -LMAX));
        }
        es0 += __shfl_xor_sync(0xffffffffu, es0, 1);
        es0 += __shfl_xor_sync(0xffffffffu, es0, 2);
        es1 += __shfl_xor_sync(0xffffffffu, es1, 1);
        es1 += __shfl_xor_sync(0xffffffffu, es1, 2);
        if ((lane & 3) == 0) {
            atomicAdd(&g_rowsum[rbase + mt * 16], es0);
            atomicAdd(&g_rowsum[rbase + mt * 16 + 8], es1);
        }
    }
}

// ---------------------------------------------------------------------------
// Kernel 3: finalize — exact fp32 target dot + target norm, margin swap, nll;
// atomic mean accumulation into out[0] (zeroed by xnorm).
// ---------------------------------------------------------------------------
__global__ void finalize_kernel(const float* __restrict__ w,
                                const int* __restrict__ tgt,
                                float* __restrict__ out) {
    const int b = blockIdx.x;
    const int tid = threadIdx.x;   // 256
    __shared__ float sd[256], sn[256];

    const int t = tgt[b];
    const float* wr = w + (size_t)t * D_SZ;
    const float* xr = g_xn + (size_t)b * D_SZ;
    float w0 = wr[tid], w1 = wr[tid + 256];
    sd[tid] = xr[tid] * w0 + xr[tid + 256] * w1;
    sn[tid] = w0 * w0 + w1 * w1;
    __syncthreads();
    #pragma unroll
    for (int off = 128; off > 0; off >>= 1) {
        if (tid < off) { sd[tid] += sd[tid + off]; sn[tid] += sn[tid + off]; }
        __syncthreads();
    }

    if (tid == 0) {
        float winv = 1.f / fmaxf(sqrtf(sn[0]), 1e-12f);
        float cosv = sd[0] * winv;
        float sinv = sqrtf(fmaxf(1.f - cosv * cosv, 0.f));
        float phi = cosv * COS_M - sinv * SIN_M;
        float adj = (cosv > 0.f) ? phi : cosv;          // easy margin
        float lt = S_SCALE * adj;
        float lo = S_SCALE * cosv;
        float s2 = g_rowsum[b] - expf(lo - LMAX) + expf(lt - LMAX);
        float nll = LMAX + logf(s2) - lt;
        atomicAdd(out, nll * (1.f / (float)B_SZ));
    }
}

// ---------------------------------------------------------------------------
extern "C" void kernel_launch(void* const* d_in, const int* in_sizes, int n_in,
                              void* d_out, int out_size) {
    const float* x = (const float*)d_in[0];
    const float* w = (const float*)d_in[1];
    const int* tgt = (const int*)d_in[2];
    float* out = (float*)d_out;

    cudaFuncSetAttribute(gemm_fused_kernel,
                         cudaFuncAttributeMaxDynamicSharedMemorySize, SMEM_BYTES);

    xnorm_kernel<<<B_SZ, 128>>>(x, out);
    dim3 grid(B_SZ / BM, NTILES_N);
    gemm_fused_kernel<<<grid, 256, SMEM_BYTES>>>(w);
    finalize_kernel<<<B_SZ, 256>>>(w, tgt, out);
}